// round 10
// baseline (speedup 1.0000x reference)
#include <cuda_runtime.h>
#include <cuda_fp16.h>
#include <cstdint>

#define B 8192
#define D 256
#define NT 64
#define NCTA (NT * (NT + 1) / 2)  // 2080 upper-triangular tiles

__device__ __half g_xh[B * D];
__device__ unsigned int g_pos_bits[B];   // bits of (posmax + 1.0f); 0 = none
__device__ unsigned int g_neg_bits[B];   // bits of (4.0f - negmin); 0 = none (atomicMax)
__device__ int g_flags[NT];              // row-block normalized flags (0 initially)
__device__ float g_sum;
__device__ int   g_cnt;
__device__ unsigned int g_done;

// ---- dynamic smem layout (bytes)
#define SM_A     0                 // 8 slabs x [128][32] halves = 65536
#define SM_B0    65536             // 8192
#define SM_B1    73728             // 8192
#define SM_JLAB  81920             // 512
#define SM_RPOS  82432             // [2][128] f32 = 1024
#define SM_RNEG  83456             // 1024
#define SM_CPOS  84480             // [4][128] f32 = 2048
#define SM_CNEG  86528             // 2048
#define SMEM_TOTAL 88576

__device__ __forceinline__ uint32_t smem_u32(const void* p) {
    uint32_t a;
    asm("{ .reg .u64 t; cvta.to.shared.u64 t, %1; cvt.u32.u64 %0, t; }" : "=r"(a) : "l"(p));
    return a;
}

__device__ __forceinline__ uint32_t swz(int r, int c) {
    return (uint32_t)(r * 64 + ((c ^ ((r >> 1) & 3)) << 4));
}

#define CP_ASYNC16(dst, src) \
    asm volatile("cp.async.cg.shared.global [%0], [%1], 16;" :: "r"(dst), "l"(src) : "memory")
#define CP_COMMIT() asm volatile("cp.async.commit_group;" ::: "memory")

__device__ __forceinline__ void ldsm_x4(uint32_t* f, uint32_t addr) {
    asm volatile("ldmatrix.sync.aligned.m8n8.x4.shared.b16 {%0,%1,%2,%3}, [%4];"
                 : "=r"(f[0]), "=r"(f[1]), "=r"(f[2]), "=r"(f[3]) : "r"(addr));
}

__device__ __forceinline__ void mma16816(float* d, const uint32_t* a, uint32_t b0, uint32_t b1) {
    asm volatile(
        "mma.sync.aligned.m16n8k16.row.col.f32.f16.f16.f32 "
        "{%0,%1,%2,%3}, {%4,%5,%6,%7}, {%8,%9}, {%0,%1,%2,%3};"
        : "+f"(d[0]), "+f"(d[1]), "+f"(d[2]), "+f"(d[3])
        : "r"(a[0]), "r"(a[1]), "r"(a[2]), "r"(a[3]), "r"(b0), "r"(b1));
}

__device__ __forceinline__ int flag_acquire(const int* p) {
    int f;
    asm volatile("ld.acquire.gpu.global.b32 %0, [%1];" : "=r"(f) : "l"(p) : "memory");
    return f;
}

// ====================== fused tile kernel (normalize folded into wave 1) ======================
__global__ __launch_bounds__(256, 2) void tile_kernel(const float* __restrict__ emb,
                                                      const int* __restrict__ labels) {
    const int g = blockIdx.x;
    int ti = (int)((129.0f - sqrtf(16641.0f - 8.0f * (float)g)) * 0.5f);
    while ((ti + 1) * (129 - (ti + 1)) / 2 <= g) ti++;
    while (ti * (129 - ti) / 2 > g) ti--;
    const int tj = ti + (g - ti * (129 - ti) / 2);

    extern __shared__ char smem[];
    const uint32_t sb = smem_u32(smem);
    const int tid = threadIdx.x;
    const int lane = tid & 31, wid = tid >> 5;
    const int wm = wid & 3, wn = wid >> 2;     // warp grid 4(m) x 2(n)
    const int i0 = ti * 128;
    const int j0 = tj * 128;

    if (tid < 128) ((int*)(smem + SM_JLAB))[tid] = labels[j0 + tid];

    // ---- phase 0: CTAs 0..63 normalize one 128-row block each ----
    if (g < NT) {
        #pragma unroll 1
        for (int pass = 0; pass < 4; pass++) {
            const int row0 = g * 128 + pass * 32 + wid * 4;
            float4 a[4], b[4];
            #pragma unroll
            for (int r = 0; r < 4; r++) {
                const float4* s = (const float4*)&emb[(size_t)(row0 + r) * D];
                a[r] = s[lane];
                b[r] = s[lane + 32];
            }
            float ss[4];
            #pragma unroll
            for (int r = 0; r < 4; r++)
                ss[r] = a[r].x*a[r].x + a[r].y*a[r].y + a[r].z*a[r].z + a[r].w*a[r].w
                      + b[r].x*b[r].x + b[r].y*b[r].y + b[r].z*b[r].z + b[r].w*b[r].w;
            #pragma unroll
            for (int o = 16; o > 0; o >>= 1) {
                #pragma unroll
                for (int r = 0; r < 4; r++) ss[r] += __shfl_xor_sync(0xffffffffu, ss[r], o);
            }
            #pragma unroll
            for (int r = 0; r < 4; r++) {
                const float inv = 1.0f / fmaxf(sqrtf(ss[r]), 1e-12f);
                uint2 lo, hi;
                __half2 h;
                h = __floats2half2_rn(a[r].x * inv, a[r].y * inv); lo.x = *(uint32_t*)&h;
                h = __floats2half2_rn(a[r].z * inv, a[r].w * inv); lo.y = *(uint32_t*)&h;
                h = __floats2half2_rn(b[r].x * inv, b[r].y * inv); hi.x = *(uint32_t*)&h;
                h = __floats2half2_rn(b[r].z * inv, b[r].w * inv); hi.y = *(uint32_t*)&h;
                uint2* dst = (uint2*)&g_xh[(size_t)(row0 + r) * D];
                dst[lane] = lo;
                dst[lane + 32] = hi;
            }
        }
        __syncthreads();
        if (tid == 0) {
            __threadfence();
            asm volatile("st.release.gpu.global.b32 [%0], %1;" :: "l"(&g_flags[g]), "r"(1) : "memory");
        }
    }

    // ---- phase 1: wait for the two row blocks this CTA consumes ----
    if (tid == 0) {
        while (flag_acquire(&g_flags[ti]) == 0) __nanosleep(64);
        while (flag_acquire(&g_flags[tj]) == 0) __nanosleep(64);
    }
    __syncthreads();

    // ---- prologue: A tile (128 rows x 256 halves) into 8 k-slabs of [128][32]
    #pragma unroll
    for (int q = 0; q < 16; q++) {
        const int gg = q * 256 + tid;
        const int slab = gg >> 9, w = gg & 511, r = w >> 2, c = w & 3;
        CP_ASYNC16(sb + SM_A + slab * 8192 + swz(r, c),
                   &g_xh[(size_t)(i0 + r) * D + slab * 32 + c * 8]);
    }
    CP_COMMIT();

    // B slab kk=0 -> buf0
    #pragma unroll
    for (int q = 0; q < 2; q++) {
        const int w = q * 256 + tid, r = w >> 2, c = w & 3;
        CP_ASYNC16(sb + SM_B0 + swz(r, c), &g_xh[(size_t)(j0 + r) * D + c * 8]);
    }
    CP_COMMIT();

    // per-lane ldmatrix offsets
    const int lr = (lane & 7) + ((lane >> 3) & 1) * 8;
    const int lc = lane >> 4;
    uint32_t a_off[2][2], b_off[4][2];
    #pragma unroll
    for (int mi = 0; mi < 2; mi++) {
        const int rA = wm * 32 + mi * 16 + lr;
        #pragma unroll
        for (int ks = 0; ks < 2; ks++) a_off[mi][ks] = swz(rA, 2 * ks + lc);
    }
    #pragma unroll
    for (int pr = 0; pr < 4; pr++) {
        const int rB = wn * 64 + pr * 16 + lr;
        #pragma unroll
        for (int ks = 0; ks < 2; ks++) b_off[pr][ks] = swz(rB, 2 * ks + lc);
    }

    int labm[2][2];
    #pragma unroll
    for (int mi = 0; mi < 2; mi++)
        #pragma unroll
        for (int hb = 0; hb < 2; hb++)
            labm[mi][hb] = __ldg(&labels[i0 + wm * 32 + mi * 16 + hb * 8 + (lane >> 2)]);

    float d[2][8][4];
    #pragma unroll
    for (int mi = 0; mi < 2; mi++)
        #pragma unroll
        for (int ni = 0; ni < 8; ni++)
            #pragma unroll
            for (int e = 0; e < 4; e++) d[mi][ni][e] = 0.0f;

    #pragma unroll
    for (int kk = 0; kk < 8; kk++) {
        if (kk < 7) {
            const uint32_t buf = sb + ((kk & 1) ? SM_B0 : SM_B1);
            #pragma unroll
            for (int q = 0; q < 2; q++) {
                const int w = q * 256 + tid, r = w >> 2, c = w & 3;
                CP_ASYNC16(buf + swz(r, c),
                           &g_xh[(size_t)(j0 + r) * D + (kk + 1) * 32 + c * 8]);
            }
            CP_COMMIT();
            asm volatile("cp.async.wait_group 1;" ::: "memory");
        } else {
            asm volatile("cp.async.wait_group 0;" ::: "memory");
        }
        __syncthreads();

        const uint32_t sa = sb + SM_A + kk * 8192;
        const uint32_t sbuf = sb + ((kk & 1) ? SM_B1 : SM_B0);
        #pragma unroll
        for (int ks = 0; ks < 2; ks++) {
            uint32_t a[2][4];
            ldsm_x4(a[0], sa + a_off[0][ks]);
            ldsm_x4(a[1], sa + a_off[1][ks]);
            uint32_t bf[4][4];
            #pragma unroll
            for (int pr = 0; pr < 4; pr++) ldsm_x4(bf[pr], sbuf + b_off[pr][ks]);
            #pragma unroll
            for (int mi = 0; mi < 2; mi++)
                #pragma unroll
                for (int pr = 0; pr < 4; pr++)
                    #pragma unroll
                    for (int sub = 0; sub < 2; sub++)
                        mma16816(d[mi][pr * 2 + sub], a[mi], bf[pr][sub], bf[pr][sub + 2]);
        }
        __syncthreads();
    }

    // ================= fused epilogue: row + column mining =================
    const int* jl = (const int*)(smem + SM_JLAB);
    float* scpos = (float*)(smem + SM_CPOS);
    float* scneg = (float*)(smem + SM_CNEG);

    float posmax[2][2], negmin[2][2];
    #pragma unroll
    for (int mi = 0; mi < 2; mi++)
        #pragma unroll
        for (int hb = 0; hb < 2; hb++) { posmax[mi][hb] = -1e9f; negmin[mi][hb] = 1e9f; }

    #pragma unroll
    for (int ni = 0; ni < 8; ni++) {
        const int colb = wn * 64 + ni * 8 + (lane & 3) * 2;
        const int l0 = jl[colb], l1 = jl[colb + 1];
        const int n0 = j0 + colb;
        float cp[2] = {-1e9f, -1e9f}, cn[2] = {1e9f, 1e9f};
        #pragma unroll
        for (int mi = 0; mi < 2; mi++) {
            #pragma unroll
            for (int e = 0; e < 4; e++) {
                const int hb = e >> 1, c01 = e & 1;
                const int m = i0 + wm * 32 + mi * 16 + hb * 8 + (lane >> 2);
                const int n = n0 + c01;
                const int ln = c01 ? l1 : l0;
                const float dist = fmaxf(1.0f - d[mi][ni][e], 0.0f);
                if (ln == labm[mi][hb]) {
                    if (m != n) {
                        posmax[mi][hb] = fmaxf(posmax[mi][hb], dist);
                        cp[c01] = fmaxf(cp[c01], dist);
                    }
                } else {
                    negmin[mi][hb] = fminf(negmin[mi][hb], dist);
                    cn[c01] = fminf(cn[c01], dist);
                }
            }
        }
        #pragma unroll
        for (int off = 4; off <= 16; off <<= 1) {
            cp[0] = fmaxf(cp[0], __shfl_xor_sync(0xffffffffu, cp[0], off));
            cp[1] = fmaxf(cp[1], __shfl_xor_sync(0xffffffffu, cp[1], off));
            cn[0] = fminf(cn[0], __shfl_xor_sync(0xffffffffu, cn[0], off));
            cn[1] = fminf(cn[1], __shfl_xor_sync(0xffffffffu, cn[1], off));
        }
        if (lane < 4) {
            const int cidx = wn * 64 + ni * 8 + lane * 2;
            scpos[wm * 128 + cidx]     = cp[0];
            scpos[wm * 128 + cidx + 1] = cp[1];
            scneg[wm * 128 + cidx]     = cn[0];
            scneg[wm * 128 + cidx + 1] = cn[1];
        }
    }

    // reduce row partials across the 4 lanes sharing each row
    #pragma unroll
    for (int mi = 0; mi < 2; mi++)
        #pragma unroll
        for (int hb = 0; hb < 2; hb++) {
            #pragma unroll
            for (int off = 1; off <= 2; off <<= 1) {
                posmax[mi][hb] = fmaxf(posmax[mi][hb], __shfl_xor_sync(0xffffffffu, posmax[mi][hb], off));
                negmin[mi][hb] = fminf(negmin[mi][hb], __shfl_xor_sync(0xffffffffu, negmin[mi][hb], off));
            }
        }
    float* srpos = (float*)(smem + SM_RPOS);
    float* srneg = (float*)(smem + SM_RNEG);
    if ((lane & 3) == 0) {
        const int gid = lane >> 2;
        #pragma unroll
        for (int mi = 0; mi < 2; mi++)
            #pragma unroll
            for (int hb = 0; hb < 2; hb++) {
                const int row = wm * 32 + mi * 16 + hb * 8 + gid;
                srpos[wn * 128 + row] = posmax[mi][hb];
                srneg[wn * 128 + row] = negmin[mi][hb];
            }
    }
    __syncthreads();
    if (tid < 128) {
        // row anchors (block ti)
        const float pv = fmaxf(srpos[tid], srpos[128 + tid]);
        const float nv = fminf(srneg[tid], srneg[128 + tid]);
        if (pv > -1e8f) atomicMax(&g_pos_bits[i0 + tid], __float_as_uint(pv + 1.0f));
        if (nv < 1e8f)  atomicMax(&g_neg_bits[i0 + tid], __float_as_uint(4.0f - nv));
        // column anchors (block tj) via symmetry (skip on diagonal)
        if (ti != tj) {
            const float cp = fmaxf(fmaxf(scpos[tid], scpos[128 + tid]),
                                   fmaxf(scpos[256 + tid], scpos[384 + tid]));
            const float cn = fminf(fminf(scneg[tid], scneg[128 + tid]),
                                   fminf(scneg[256 + tid], scneg[384 + tid]));
            if (cp > -1e8f) atomicMax(&g_pos_bits[j0 + tid], __float_as_uint(cp + 1.0f));
            if (cn < 1e8f)  atomicMax(&g_neg_bits[j0 + tid], __float_as_uint(4.0f - cn));
        }
    }
}

// ====================== combine + fused finalize + state reset ======================
#define CBLOCKS 32
__global__ void combine_kernel(float* __restrict__ out) {
    const int row = blockIdx.x * 256 + threadIdx.x;
    const float pf = __uint_as_float(g_pos_bits[row]);   // posmax + 1 ; 0 = none
    const float nf = __uint_as_float(g_neg_bits[row]);   // 4 - negmin ; 0 = none
    const bool valid = (pf > 0.0f) && (nf > 0.0f);
    // per = max(posmax - negmin + 1, 0) = max((pf-1) - (4-nf) + 1, 0)
    const float per = valid ? fmaxf(pf + nf - 4.0f, 0.0f) : 0.0f;  // MARGIN = 1.0
    const int cnt = valid ? 1 : 0;

    // reset state for the next graph replay
    g_pos_bits[row] = 0u;
    g_neg_bits[row] = 0u;
    if (blockIdx.x == 0 && threadIdx.x < NT) g_flags[threadIdx.x] = 0;

    __shared__ float ss[256];
    __shared__ int sc[256];
    const int t = threadIdx.x;
    ss[t] = per; sc[t] = cnt;
    __syncthreads();
    #pragma unroll
    for (int s = 128; s > 0; s >>= 1) {
        if (t < s) { ss[t] += ss[t + s]; sc[t] += sc[t + s]; }
        __syncthreads();
    }
    if (t == 0) {
        atomicAdd(&g_sum, ss[0]);
        atomicAdd(&g_cnt, sc[0]);
        __threadfence();
        const unsigned int rank = atomicAdd(&g_done, 1u);
        if (rank == CBLOCKS - 1) {
            const float total = atomicAdd(&g_sum, 0.0f);
            const int c = atomicAdd(&g_cnt, 0);
            const float cf = (float)c;
            out[0] = (cf > 0.0f) ? (total / fmaxf(cf, 1.0f)) : 0.0f;
            // reset accumulators for next replay
            g_sum = 0.0f;
            g_cnt = 0;
            g_done = 0u;
        }
    }
}

// ======================================================================
extern "C" void kernel_launch(void* const* d_in, const int* in_sizes, int n_in,
                              void* d_out, int out_size) {
    const float* emb = (const float*)d_in[0];
    const int* labels = (const int*)d_in[1];
    float* out = (float*)d_out;

    cudaFuncSetAttribute(tile_kernel, cudaFuncAttributeMaxDynamicSharedMemorySize, SMEM_TOTAL);

    tile_kernel<<<NCTA, 256, SMEM_TOTAL>>>(emb, labels);
    combine_kernel<<<CBLOCKS, 256>>>(out);
}

// round 11
// speedup vs baseline: 1.1235x; 1.1235x over previous
#include <cuda_runtime.h>
#include <cuda_fp16.h>
#include <cstdint>

#define B 8192
#define D 256
#define NT 64
#define NCTA (NT * (NT + 1) / 2)  // 2080 upper-triangular tiles

__device__ __half g_xh[B * D];
__device__ unsigned int g_pos_bits[B];   // bits of (posmax + 1.0f); 0 = none (atomicMax)
__device__ unsigned int g_neg_bits[B];   // bits of negmin; init bits(1e9) (atomicMin)
__device__ float g_sum;
__device__ int   g_cnt;
__device__ unsigned int g_done;

// ---- dynamic smem layout (bytes)
#define SM_A     0                  // 8 slabs x [128][32] halves = 65536
#define SM_B     65536              // 4-slab ring x 8192 = 32768
#define SM_JLAB  98304              // 512
#define SM_RPOS  98816              // [2][128] f32 = 1024
#define SM_RNEG  99840              // 1024
#define SM_CPOS  100864             // [4][128] f32 = 2048
#define SM_CNEG  102912             // 2048
#define SMEM_TOTAL 104960           // x2 CTAs = 209920 < 227328

__device__ __forceinline__ uint32_t smem_u32(const void* p) {
    uint32_t a;
    asm("{ .reg .u64 t; cvta.to.shared.u64 t, %1; cvt.u32.u64 %0, t; }" : "=r"(a) : "l"(p));
    return a;
}

__device__ __forceinline__ uint32_t swz(int r, int c) {
    return (uint32_t)(r * 64 + ((c ^ ((r >> 1) & 3)) << 4));
}

#define CP_ASYNC16(dst, src) \
    asm volatile("cp.async.cg.shared.global [%0], [%1], 16;" :: "r"(dst), "l"(src) : "memory")
#define CP_COMMIT() asm volatile("cp.async.commit_group;" ::: "memory")

__device__ __forceinline__ void ldsm_x4(uint32_t* f, uint32_t addr) {
    asm volatile("ldmatrix.sync.aligned.m8n8.x4.shared.b16 {%0,%1,%2,%3}, [%4];"
                 : "=r"(f[0]), "=r"(f[1]), "=r"(f[2]), "=r"(f[3]) : "r"(addr));
}

__device__ __forceinline__ void mma16816(float* d, const uint32_t* a, uint32_t b0, uint32_t b1) {
    asm volatile(
        "mma.sync.aligned.m16n8k16.row.col.f32.f16.f16.f32 "
        "{%0,%1,%2,%3}, {%4,%5,%6,%7}, {%8,%9}, {%0,%1,%2,%3};"
        : "+f"(d[0]), "+f"(d[1]), "+f"(d[2]), "+f"(d[3])
        : "r"(a[0]), "r"(a[1]), "r"(a[2]), "r"(a[3]), "r"(b0), "r"(b1));
}

// ====================== 1) normalize -> fp16 (2 rows per warp) + init ======================
__global__ void normalize_kernel(const float* __restrict__ x) {
    const int gid = blockIdx.x * 256 + threadIdx.x;
    // 512 blocks x 256 = 131072 threads; init sinks on first 8192
    if (gid < B) {
        g_pos_bits[gid] = 0u;
        g_neg_bits[gid] = __float_as_uint(1e9f);
    }
    if (gid == 0) { g_sum = 0.0f; g_cnt = 0; g_done = 0u; }

    const int warp = gid >> 5;
    const int lane = threadIdx.x & 31;
    const int row0 = warp * 2;

    const float4* s0 = (const float4*)&x[(size_t)row0 * D];
    const float4* s1 = (const float4*)&x[(size_t)(row0 + 1) * D];
    float4 a = s0[lane], b = s0[lane + 32];
    float4 c = s1[lane], e = s1[lane + 32];

    float sA = a.x*a.x + a.y*a.y + a.z*a.z + a.w*a.w
             + b.x*b.x + b.y*b.y + b.z*b.z + b.w*b.w;
    float sB = c.x*c.x + c.y*c.y + c.z*c.z + c.w*c.w
             + e.x*e.x + e.y*e.y + e.z*e.z + e.w*e.w;
    #pragma unroll
    for (int o = 16; o > 0; o >>= 1) {
        sA += __shfl_xor_sync(0xffffffffu, sA, o);
        sB += __shfl_xor_sync(0xffffffffu, sB, o);
    }
    const float invA = 1.0f / fmaxf(sqrtf(sA), 1e-12f);
    const float invB = 1.0f / fmaxf(sqrtf(sB), 1e-12f);

    uint2 lo, hi; __half2 h;
    h = __floats2half2_rn(a.x * invA, a.y * invA); lo.x = *(uint32_t*)&h;
    h = __floats2half2_rn(a.z * invA, a.w * invA); lo.y = *(uint32_t*)&h;
    h = __floats2half2_rn(b.x * invA, b.y * invA); hi.x = *(uint32_t*)&h;
    h = __floats2half2_rn(b.z * invA, b.w * invA); hi.y = *(uint32_t*)&h;
    uint2* d0 = (uint2*)&g_xh[(size_t)row0 * D];
    d0[lane] = lo; d0[lane + 32] = hi;
    h = __floats2half2_rn(c.x * invB, c.y * invB); lo.x = *(uint32_t*)&h;
    h = __floats2half2_rn(c.z * invB, c.w * invB); lo.y = *(uint32_t*)&h;
    h = __floats2half2_rn(e.x * invB, e.y * invB); hi.x = *(uint32_t*)&h;
    h = __floats2half2_rn(e.z * invB, e.w * invB); hi.y = *(uint32_t*)&h;
    uint2* d1 = (uint2*)&g_xh[(size_t)(row0 + 1) * D];
    d1[lane] = lo; d1[lane + 32] = hi;
}

// ====================== 2) upper-triangular fused tile kernel ======================
// 4-slab B ring, 2 k-slabs per barrier pair (8 barriers/tile instead of 16).
__global__ __launch_bounds__(256, 2) void tile_kernel(const int* __restrict__ labels) {
    const int g = blockIdx.x;
    int ti = (int)((129.0f - sqrtf(16641.0f - 8.0f * (float)g)) * 0.5f);
    while ((ti + 1) * (129 - (ti + 1)) / 2 <= g) ti++;
    while (ti * (129 - ti) / 2 > g) ti--;
    const int tj = ti + (g - ti * (129 - ti) / 2);

    extern __shared__ char smem[];
    const uint32_t sb = smem_u32(smem);
    const int tid = threadIdx.x;
    const int lane = tid & 31, wid = tid >> 5;
    const int wm = wid & 3, wn = wid >> 2;     // warp grid 4(m) x 2(n)
    const int i0 = ti * 128;
    const int j0 = tj * 128;

    if (tid < 128) ((int*)(smem + SM_JLAB))[tid] = labels[j0 + tid];

    const int bw = tid >> 2, bc = tid & 3;     // B-slab load coords (first 512 "w" per q)
    // ---- group 0: A tile (16 cp) + B slabs 0,1 (4 cp)
    #pragma unroll
    for (int q = 0; q < 16; q++) {
        const int gg = q * 256 + tid;
        const int slab = gg >> 9, w = gg & 511, r = w >> 2, c = w & 3;
        CP_ASYNC16(sb + SM_A + slab * 8192 + swz(r, c),
                   &g_xh[(size_t)(i0 + r) * D + slab * 32 + c * 8]);
    }
    #pragma unroll
    for (int s = 0; s < 2; s++) {
        #pragma unroll
        for (int q = 0; q < 2; q++) {
            const int w = q * 256 + tid, r = w >> 2, c = w & 3;
            CP_ASYNC16(sb + SM_B + s * 8192 + swz(r, c),
                       &g_xh[(size_t)(j0 + r) * D + s * 32 + c * 8]);
        }
    }
    CP_COMMIT();
    // groups 1,2: B slabs 2,3
    #pragma unroll
    for (int s = 2; s < 4; s++) {
        #pragma unroll
        for (int q = 0; q < 2; q++) {
            const int w = q * 256 + tid, r = w >> 2, c = w & 3;
            CP_ASYNC16(sb + SM_B + s * 8192 + swz(r, c),
                       &g_xh[(size_t)(j0 + r) * D + s * 32 + c * 8]);
        }
        CP_COMMIT();
    }

    // per-lane ldmatrix offsets
    const int lr = (lane & 7) + ((lane >> 3) & 1) * 8;
    const int lc = lane >> 4;
    uint32_t a_off[2][2], b_off[4][2];
    #pragma unroll
    for (int mi = 0; mi < 2; mi++) {
        const int rA = wm * 32 + mi * 16 + lr;
        #pragma unroll
        for (int ks = 0; ks < 2; ks++) a_off[mi][ks] = swz(rA, 2 * ks + lc);
    }
    #pragma unroll
    for (int pr = 0; pr < 4; pr++) {
        const int rB = wn * 64 + pr * 16 + lr;
        #pragma unroll
        for (int ks = 0; ks < 2; ks++) b_off[pr][ks] = swz(rB, 2 * ks + lc);
    }

    int labm[2][2];
    #pragma unroll
    for (int mi = 0; mi < 2; mi++)
        #pragma unroll
        for (int hb = 0; hb < 2; hb++)
            labm[mi][hb] = __ldg(&labels[i0 + wm * 32 + mi * 16 + hb * 8 + (lane >> 2)]);

    float d[2][8][4];
    #pragma unroll
    for (int mi = 0; mi < 2; mi++)
        #pragma unroll
        for (int ni = 0; ni < 8; ni++)
            #pragma unroll
            for (int e = 0; e < 4; e++) d[mi][ni][e] = 0.0f;

    // ---- main loop: 2 slabs per barrier pair ----
    #pragma unroll
    for (int kk = 0; kk < 8; kk += 2) {
        if (kk < 6) {
            asm volatile("cp.async.wait_group 2;" ::: "memory");
        } else {
            asm volatile("cp.async.wait_group 0;" ::: "memory");
        }
        __syncthreads();

        #pragma unroll
        for (int s2 = 0; s2 < 2; s2++) {
            const int slab = kk + s2;
            const uint32_t sa = sb + SM_A + slab * 8192;
            const uint32_t sbuf = sb + SM_B + (slab & 3) * 8192;
            #pragma unroll
            for (int ks = 0; ks < 2; ks++) {
                uint32_t a[2][4];
                ldsm_x4(a[0], sa + a_off[0][ks]);
                ldsm_x4(a[1], sa + a_off[1][ks]);
                uint32_t bf[4][4];
                #pragma unroll
                for (int pr = 0; pr < 4; pr++) ldsm_x4(bf[pr], sbuf + b_off[pr][ks]);
                #pragma unroll
                for (int mi = 0; mi < 2; mi++)
                    #pragma unroll
                    for (int pr = 0; pr < 4; pr++)
                        #pragma unroll
                        for (int sub = 0; sub < 2; sub++)
                            mma16816(d[mi][pr * 2 + sub], a[mi], bf[pr][sub], bf[pr][sub + 2]);
            }
        }
        __syncthreads();

        if (kk < 4) {
            #pragma unroll
            for (int s2 = 0; s2 < 2; s2++) {
                const int s = kk + 4 + s2;
                #pragma unroll
                for (int q = 0; q < 2; q++) {
                    const int w = q * 256 + tid, r = w >> 2, c = w & 3;
                    CP_ASYNC16(sb + SM_B + (s & 3) * 8192 + swz(r, c),
                               &g_xh[(size_t)(j0 + r) * D + s * 32 + c * 8]);
                }
                CP_COMMIT();
            }
        }
    }

    // ================= fused epilogue: row + column mining =================
    const int* jl = (const int*)(smem + SM_JLAB);
    float* scpos = (float*)(smem + SM_CPOS);
    float* scneg = (float*)(smem + SM_CNEG);

    float posmax[2][2], negmin[2][2];
    #pragma unroll
    for (int mi = 0; mi < 2; mi++)
        #pragma unroll
        for (int hb = 0; hb < 2; hb++) { posmax[mi][hb] = -1e9f; negmin[mi][hb] = 1e9f; }

    #pragma unroll
    for (int ni = 0; ni < 8; ni++) {
        const int colb = wn * 64 + ni * 8 + (lane & 3) * 2;
        const int l0 = jl[colb], l1 = jl[colb + 1];
        const int n0 = j0 + colb;
        float cp[2] = {-1e9f, -1e9f}, cn[2] = {1e9f, 1e9f};
        #pragma unroll
        for (int mi = 0; mi < 2; mi++) {
            #pragma unroll
            for (int e = 0; e < 4; e++) {
                const int hb = e >> 1, c01 = e & 1;
                const int m = i0 + wm * 32 + mi * 16 + hb * 8 + (lane >> 2);
                const int n = n0 + c01;
                const int ln = c01 ? l1 : l0;
                const float dist = fmaxf(1.0f - d[mi][ni][e], 0.0f);
                if (ln == labm[mi][hb]) {
                    if (m != n) {
                        posmax[mi][hb] = fmaxf(posmax[mi][hb], dist);
                        cp[c01] = fmaxf(cp[c01], dist);
                    }
                } else {
                    negmin[mi][hb] = fminf(negmin[mi][hb], dist);
                    cn[c01] = fminf(cn[c01], dist);
                }
            }
        }
        #pragma unroll
        for (int off = 4; off <= 16; off <<= 1) {
            cp[0] = fmaxf(cp[0], __shfl_xor_sync(0xffffffffu, cp[0], off));
            cp[1] = fmaxf(cp[1], __shfl_xor_sync(0xffffffffu, cp[1], off));
            cn[0] = fminf(cn[0], __shfl_xor_sync(0xffffffffu, cn[0], off));
            cn[1] = fminf(cn[1], __shfl_xor_sync(0xffffffffu, cn[1], off));
        }
        if (lane < 4) {
            const int cidx = wn * 64 + ni * 8 + lane * 2;
            scpos[wm * 128 + cidx]     = cp[0];
            scpos[wm * 128 + cidx + 1] = cp[1];
            scneg[wm * 128 + cidx]     = cn[0];
            scneg[wm * 128 + cidx + 1] = cn[1];
        }
    }

    // reduce row partials across the 4 lanes sharing each row
    #pragma unroll
    for (int mi = 0; mi < 2; mi++)
        #pragma unroll
        for (int hb = 0; hb < 2; hb++) {
            #pragma unroll
            for (int off = 1; off <= 2; off <<= 1) {
                posmax[mi][hb] = fmaxf(posmax[mi][hb], __shfl_xor_sync(0xffffffffu, posmax[mi][hb], off));
                negmin[mi][hb] = fminf(negmin[mi][hb], __shfl_xor_sync(0xffffffffu, negmin[mi][hb], off));
            }
        }
    float* srpos = (float*)(smem + SM_RPOS);
    float* srneg = (float*)(smem + SM_RNEG);
    if ((lane & 3) == 0) {
        const int gid = lane >> 2;
        #pragma unroll
        for (int mi = 0; mi < 2; mi++)
            #pragma unroll
            for (int hb = 0; hb < 2; hb++) {
                const int row = wm * 32 + mi * 16 + hb * 8 + gid;
                srpos[wn * 128 + row] = posmax[mi][hb];
                srneg[wn * 128 + row] = negmin[mi][hb];
            }
    }
    __syncthreads();
    if (tid < 128) {
        // row anchors (block ti)
        const float pv = fmaxf(srpos[tid], srpos[128 + tid]);
        const float nv = fminf(srneg[tid], srneg[128 + tid]);
        if (pv > -1e8f) atomicMax(&g_pos_bits[i0 + tid], __float_as_uint(pv + 1.0f));
        if (nv < 1e8f)  atomicMin(&g_neg_bits[i0 + tid], __float_as_uint(nv));
        // column anchors (block tj) via symmetry (skip on diagonal)
        if (ti != tj) {
            const float cp = fmaxf(fmaxf(scpos[tid], scpos[128 + tid]),
                                   fmaxf(scpos[256 + tid], scpos[384 + tid]));
            const float cn = fminf(fminf(scneg[tid], scneg[128 + tid]),
                                   fminf(scneg[256 + tid], scneg[384 + tid]));
            if (cp > -1e8f) atomicMax(&g_pos_bits[j0 + tid], __float_as_uint(cp + 1.0f));
            if (cn < 1e8f)  atomicMin(&g_neg_bits[j0 + tid], __float_as_uint(cn));
        }
    }
}

// ====================== 3) combine + fused finalize ======================
#define CBLOCKS 32
__global__ void combine_kernel(float* __restrict__ out) {
    const int row = blockIdx.x * 256 + threadIdx.x;
    const float pf = __uint_as_float(g_pos_bits[row]);
    const float nf = __uint_as_float(g_neg_bits[row]);
    const bool valid = (pf >= 1.0f) && (nf < 1e8f);
    const float per = valid ? fmaxf((pf - 1.0f) - nf + 1.0f, 0.0f) : 0.0f;  // MARGIN = 1.0
    const int cnt = valid ? 1 : 0;

    __shared__ float ss[256];
    __shared__ int sc[256];
    const int t = threadIdx.x;
    ss[t] = per; sc[t] = cnt;
    __syncthreads();
    #pragma unroll
    for (int s = 128; s > 0; s >>= 1) {
        if (t < s) { ss[t] += ss[t + s]; sc[t] += sc[t + s]; }
        __syncthreads();
    }
    if (t == 0) {
        atomicAdd(&g_sum, ss[0]);
        atomicAdd(&g_cnt, sc[0]);
        __threadfence();
        const unsigned int rank = atomicAdd(&g_done, 1u);
        if (rank == CBLOCKS - 1) {
            const float total = atomicAdd(&g_sum, 0.0f);
            const int c = atomicAdd(&g_cnt, 0);
            const float cf = (float)c;
            out[0] = (cf > 0.0f) ? (total / fmaxf(cf, 1.0f)) : 0.0f;
        }
    }
}

// ======================================================================
extern "C" void kernel_launch(void* const* d_in, const int* in_sizes, int n_in,
                              void* d_out, int out_size) {
    const float* emb = (const float*)d_in[0];
    const int* labels = (const int*)d_in[1];
    float* out = (float*)d_out;

    cudaFuncSetAttribute(tile_kernel, cudaFuncAttributeMaxDynamicSharedMemorySize, SMEM_TOTAL);

    normalize_kernel<<<512, 256>>>(emb);             // 2 rows/warp + sink init
    tile_kernel<<<NCTA, 256, SMEM_TOTAL>>>(labels);
    combine_kernel<<<CBLOCKS, 256>>>(out);
}